// round 16
// baseline (speedup 1.0000x reference)
#include <cuda_runtime.h>
#include <cuda_fp16.h>
#include <cstdint>

#define LSEQ 2048
#define NH   8
#define DDIM 64
#define NB   4
#define NBH  32          // NB*NH
#define MDIST 128
#define DBINS 257
#define LDP  72          // padded shared row stride (halves): 144B -> conflict-free ldmatrix
#define LOG2E 1.4426950408889634f
#define SSTR 264         // replicated-bin stride (floats); disjoint bank spans per tc

// ---------------- scratch (device globals; no runtime alloc) ----------------
__device__ __half g_qkin[8192 * 256];       // x+pe, fp16
__device__ __half g_Wt[1024 * 256];         // [Wq|Wk]^T, n-major rows, k contiguous
__device__ __half g_Q[NBH * LSEQ * DDIM];   // scaled by d^-0.5 * log2(e), +bias
__device__ __half g_K[NBH * LSEQ * DDIM];
__device__ float  g_V[NBH * LSEQ];          // Vflip[b,h,k] = sigmoid(x[b,L-1-k] . Wv[:,h])

// ---------------- helpers ----------------
__device__ __forceinline__ uint32_t sptr(const void* p) {
    return (uint32_t)__cvta_generic_to_shared(p);
}

__device__ __forceinline__ uint32_t h2ex2(uint32_t x) {   // packed half2 2^x
    uint32_t r;
    asm("ex2.approx.f16x2 %0, %1;\n" : "=r"(r) : "r"(x));
    return r;
}

__device__ __forceinline__ uint32_t h2add(uint32_t a, uint32_t b) {
    uint32_t r;
    asm("add.f16x2 %0, %1, %2;\n" : "=r"(r) : "r"(a), "r"(b));
    return r;
}

__device__ __forceinline__ void ldsm4(uint32_t& r0, uint32_t& r1, uint32_t& r2, uint32_t& r3,
                                      uint32_t addr) {
    asm volatile("ldmatrix.sync.aligned.m8n8.x4.shared.b16 {%0,%1,%2,%3}, [%4];\n"
                 : "=r"(r0), "=r"(r1), "=r"(r2), "=r"(r3) : "r"(addr));
}

// f16-accumulate MMA: C/D = 2 packed-half2 regs
__device__ __forceinline__ void mma16816h(uint32_t& c0, uint32_t& c1, uint32_t a0, uint32_t a1,
                                          uint32_t a2, uint32_t a3, uint32_t b0, uint32_t b1) {
    asm volatile(
        "mma.sync.aligned.m16n8k16.row.col.f16.f16.f16.f16 "
        "{%0,%1},{%2,%3,%4,%5},{%6,%7},{%0,%1};\n"
        : "+r"(c0), "+r"(c1)
        : "r"(a0), "r"(a1), "r"(a2), "r"(a3), "r"(b0), "r"(b1));
}

__device__ __forceinline__ void cp_async16(uint32_t dst, const void* src) {
    asm volatile("cp.async.ca.shared.global [%0], [%1], 16;\n" :: "r"(dst), "l"(src));
}
__device__ __forceinline__ void cp_commit() { asm volatile("cp.async.commit_group;\n"); }
__device__ __forceinline__ void cp_wait1()  { asm volatile("cp.async.wait_group 1;\n"); }
__device__ __forceinline__ void cp_wait0()  { asm volatile("cp.async.wait_group 0;\n"); }

// async copy of a 64x64 half tile into padded shared tile (global row stride = stride)
__device__ __forceinline__ void cp_tile_s(__half* dst, const __half* src, int stride, int tid) {
    int r = tid >> 3, c = (tid & 7) << 3;
    cp_async16(sptr(dst + r * LDP + c), src + r * stride + c);
    cp_async16(sptr(dst + (r + 32) * LDP + c), src + (r + 32) * stride + c);
}

// async copy of a 128x64 half tile (global row stride = 64)
__device__ __forceinline__ void cp_tile128(__half* dst, const __half* src, int tid) {
    int r = tid >> 3, c = (tid & 7) << 3;
#pragma unroll
    for (int rr = 0; rr < 4; rr++)
        cp_async16(sptr(dst + (r + rr * 32) * LDP + c), src + (r + rr * 32) * 64 + c);
}

// Dual-subtile MMA (attention): B fragments loaded once, applied to both Q subtiles.
__device__ __forceinline__ void mma_h2(const __half* Ks, const uint32_t Af[2][4][4],
                                       uint32_t acc[2][4][2], int lane, int wx) {
    int brow = wx * 32 + (lane & 7) + ((lane >> 4) << 3);
    int bcol = ((lane >> 3) & 1) << 3;
    uint32_t b_addr0 = sptr(Ks + brow * LDP + bcol);
    uint32_t b_addr1 = b_addr0 + 16 * LDP * 2;
#pragma unroll
    for (int kc = 0; kc < 4; kc++) {
        uint32_t b0, b1, b2, b3, b4, b5, b6, b7;
        ldsm4(b0, b1, b2, b3, b_addr0 + kc * 32);
        ldsm4(b4, b5, b6, b7, b_addr1 + kc * 32);
#pragma unroll
        for (int sub = 0; sub < 2; sub++) {
            mma16816h(acc[sub][0][0], acc[sub][0][1], Af[sub][kc][0], Af[sub][kc][1],
                      Af[sub][kc][2], Af[sub][kc][3], b0, b1);
            mma16816h(acc[sub][1][0], acc[sub][1][1], Af[sub][kc][0], Af[sub][kc][1],
                      Af[sub][kc][2], Af[sub][kc][3], b2, b3);
            mma16816h(acc[sub][2][0], acc[sub][2][1], Af[sub][kc][0], Af[sub][kc][1],
                      Af[sub][kc][2], Af[sub][kc][3], b4, b5);
            mma16816h(acc[sub][3][0], acc[sub][3][1], Af[sub][kc][0], Af[sub][kc][1],
                      Af[sub][kc][2], Af[sub][kc][3], b6, b7);
        }
    }
}

// 64x64 mma, A+B from shared, f16 acc (proj kernel, 4x2 warp grid, 16x32/warp)
__device__ __forceinline__ void mma_tile_64h(const __half* Qs, const __half* Ks,
                                             uint32_t acc[4][2], int lane, int wy, int wx) {
    uint32_t a_addr = sptr(Qs + (wy * 16 + (lane & 15)) * LDP + ((lane >> 4) << 3));
    int brow = wx * 32 + (lane & 7) + ((lane >> 4) << 3);
    int bcol = ((lane >> 3) & 1) << 3;
    uint32_t b_addr0 = sptr(Ks + brow * LDP + bcol);
    uint32_t b_addr1 = b_addr0 + 16 * LDP * 2;
#pragma unroll
    for (int kc = 0; kc < 4; kc++) {
        uint32_t a0, a1, a2, a3, b0, b1, b2, b3, b4, b5, b6, b7;
        ldsm4(a0, a1, a2, a3, a_addr + kc * 32);
        ldsm4(b0, b1, b2, b3, b_addr0 + kc * 32);
        ldsm4(b4, b5, b6, b7, b_addr1 + kc * 32);
        mma16816h(acc[0][0], acc[0][1], a0, a1, a2, a3, b0, b1);
        mma16816h(acc[1][0], acc[1][1], a0, a1, a2, a3, b2, b3);
        mma16816h(acc[2][0], acc[2][1], a0, a1, a2, a3, b4, b5);
        mma16816h(acc[3][0], acc[3][1], a0, a1, a2, a3, b6, b7);
    }
}

// ---------------- kernel 1: prep (MLP-8 row blocks + tiled W transpose + out zero) ---
#define PR_BLOCKS 512           // 8192 rows / 16 rows per block
#define TR_BLOCKS 64            // 2 weights x (4 kk-tiles x 8 n-tiles)
#define XP 264                  // padded float row stride (float4-aligned)
__global__ void __launch_bounds__(256) prep_kernel(const float* __restrict__ x,
                                                   const float* __restrict__ pe,
                                                   const float* __restrict__ Wq,
                                                   const float* __restrict__ Wk,
                                                   const float* __restrict__ Wv,
                                                   float* __restrict__ out) {
    __shared__ float Sh[24 * XP];           // row blocks: Xsh[16*XP] + Wsh[8*XP]
                                            // transpose blocks: Tsh[64*65] (4160 floats)
    int bid = blockIdx.x, tid = threadIdx.x;
    if (bid < PR_BLOCKS) {
        float* Xsh = Sh;
        float* Wsh = Sh + 16 * XP;          // Wv transposed: [h][kk]
        for (int i = tid; i < 2048; i += 256) {
            int kk = i >> 3, h = i & 7;
            Wsh[h * XP + kk] = Wv[i];
        }
        int row0 = bid * 16;
        // one (row, 16-col strip) per thread: front-batched x + pe LDGs (MLP 8),
        // qkin computed straight from registers (no smem round-trip, no barrier)
        int r = tid >> 4, c0 = (tid & 15) << 4;
        int row = row0 + r;
        int l = row & (LSEQ - 1);
        float4 xv[4], pv[4];
#pragma unroll
        for (int j = 0; j < 4; j++) {
            xv[j] = *(const float4*)(x + row * 256 + c0 + 4 * j);
            pv[j] = *(const float4*)(pe + l * 256 + c0 + 4 * j);
        }
#pragma unroll
        for (int j = 0; j < 4; j++) {
            *(float4*)(Xsh + r * XP + c0 + 4 * j) = xv[j];   // x staged for V-dot only
            __half2 h0 = __floats2half2_rn(xv[j].x + pv[j].x, xv[j].y + pv[j].y);
            __half2 h1 = __floats2half2_rn(xv[j].z + pv[j].z, xv[j].w + pv[j].w);
            uint2 st;
            st.x = *(uint32_t*)&h0;
            st.y = *(uint32_t*)&h1;
            *(uint2*)(g_qkin + row * 256 + c0 + 4 * j) = st;
        }
        __syncthreads();
        // V = sigmoid(x . Wv), flipped; 2 threads per (row, h), float4 dot
        int task = tid >> 1, halfi = tid & 1;
        int rr = task >> 3, h = task & 7;
        const float* xr = Xsh + rr * XP + halfi * 128;
        const float* wr = Wsh + h * XP + halfi * 128;
        float s = 0.f;
#pragma unroll
        for (int kk = 0; kk < 128; kk += 4) {
            float4 a = *(const float4*)(xr + kk);
            float4 b = *(const float4*)(wr + kk);
            s += a.x * b.x + a.y * b.y + a.z * b.z + a.w * b.w;
        }
        s += __shfl_xor_sync(0xffffffffu, s, 1);
        if (halfi == 0) {
            int bl = row0 + rr;
            float v = 1.f / (1.f + __expf(-s));
            int b = bl >> 11, ll = bl & (LSEQ - 1);
            g_V[(b * NH + h) * LSEQ + (LSEQ - 1 - ll)] = v;
        }
    } else if (bid < PR_BLOCKS + TR_BLOCKS) {
        // coalesced tiled transpose of Wq/Wk into g_Wt (n-major, kk contiguous)
        int tb = bid - PR_BLOCKS;
        int which = tb >> 5;                // 0 = Wq, 1 = Wk
        int t = tb & 31;
        int kk0 = (t >> 3) << 6;            // 4 kk-tiles
        int n0 = (t & 7) << 6;              // 8 n-tiles
        const float* W = which ? Wk : Wq;
        float* Tsh = Sh;                    // 64 x 65 staging
        for (int i = tid; i < 4096; i += 256) {
            int r = i >> 6, c = i & 63;     // r = local kk, c = local n (coalesced read)
            Tsh[c * 65 + r] = W[(kk0 + r) * 512 + n0 + c];
        }
        __syncthreads();
        for (int i = tid; i < 4096; i += 256) {
            int n = i >> 6, kk = i & 63;    // contiguous half writes along kk
            g_Wt[(which * 512 + n0 + n) * 256 + kk0 + kk] = __float2half(Tsh[n * 65 + kk]);
        }
    } else {
        int idx = (bid - PR_BLOCKS - TR_BLOCKS) * 256 + tid;
        if (idx < NB * DBINS * NH) out[idx] = 0.f;  // attn scatters into out
    }
}

// ---------------- kernel 2: Q/K projection GEMM (f16 acc, cp.async 2-stage) ---------
__global__ void __launch_bounds__(256) proj_kernel(const float* __restrict__ bq,
                                                   const float* __restrict__ bk) {
    __shared__ __half As[2][64 * LDP];
    __shared__ __half Bs[2][64 * LDP];
    int tid = threadIdx.x, lane = tid & 31, w = tid >> 5, wy = w >> 1, wx = w & 1;
    int m0 = blockIdx.x << 6, n0 = blockIdx.y << 6;
    const __half* Ag = g_qkin + m0 * 256;
    const __half* Bg = g_Wt + n0 * 256;

    uint32_t acc[4][2];
#pragma unroll
    for (int i = 0; i < 4; i++) { acc[i][0] = 0u; acc[i][1] = 0u; }

    // stage 0
    cp_tile_s(As[0], Ag, 256, tid);
    cp_tile_s(Bs[0], Bg, 256, tid);
    cp_commit();

#define PROJ_STEP(KS, WAITN)                                                     \
    {                                                                            \
        if ((KS) + 1 < 4) {                                                      \
            cp_tile_s(As[((KS) + 1) & 1], Ag + ((KS) + 1) * 64, 256, tid);       \
            cp_tile_s(Bs[((KS) + 1) & 1], Bg + ((KS) + 1) * 64, 256, tid);       \
            cp_commit();                                                         \
        }                                                                        \
        asm volatile("cp.async.wait_group %0;\n" ::"n"(WAITN));                  \
        __syncthreads();                                                         \
        mma_tile_64h(As[(KS) & 1], Bs[(KS) & 1], acc, lane, wy, wx);             \
        __syncthreads();                                                         \
    }
    PROJ_STEP(0, 1)
    PROJ_STEP(1, 1)
    PROJ_STEP(2, 1)
    PROJ_STEP(3, 0)
#undef PROJ_STEP

    int g = lane >> 2, tc = lane & 3;
#pragma unroll
    for (int nt = 0; nt < 4; nt++) {
#pragma unroll
        for (int hh = 0; hh < 2; hh++) {
            float2 v = __half22float2(*(__half2*)&acc[nt][hh]);
            int row = m0 + wy * 16 + g + (hh << 3);
            int col = n0 + wx * 32 + nt * 8 + tc * 2;
            int b = row >> 11, l = row & (LSEQ - 1);
            if (col < 512) {
                // fold d^-0.5 and log2(e) into Q so score-exp is a single ex2
                float v0 = (v.x + bq[col]) * (0.125f * LOG2E);
                float v1 = (v.y + bq[col + 1]) * (0.125f * LOG2E);
                int hd = col >> 6, dd = col & 63;
                *(__half2*)(g_Q + ((b * NH + hd) * LSEQ + l) * DDIM + dd) =
                    __floats2half2_rn(v0, v1);
            } else {
                int cj = col - 512;
                float v0 = v.x + bk[cj];
                float v1 = v.y + bk[cj + 1];
                int hd = cj >> 6, dd = cj & 63;
                *(__half2*)(g_K + ((b * NH + hd) * LSEQ + l) * DDIM + dd) =
                    __floats2half2_rn(v0, v1);
            }
        }
    }
}

// ---------------- kernel 3: attention (128-row Q block; stencil-scatter output) ------
__global__ void __launch_bounds__(256, 4) attn_kernel(float* __restrict__ out) {
    __shared__ __half Kb[2][128 * LDP];     // double-buffered 128-key tiles; Kb[0] stages Q
    __shared__ float dsh[128];
    __shared__ float Ssh[4 * SSTR];         // 4 bank-replicated bin arrays (by tc)
    __shared__ float Vsh[3 * 128];

    int tid = threadIdx.x, lane = tid & 31, w = tid >> 5, wy = w >> 1, wx = w & 1;
    int qb = blockIdx.x, bh = blockIdx.y;   // qb: 128-row Q block (0..15)
    int q0 = qb << 7;
    const __half* Qg = g_Q + (bh * LSEQ + q0) * DDIM;
    const __half* Kg = g_K + bh * LSEQ * DDIM;

    // band 128-key tiles for q in [q0, q0+127]: k in [q0-128, q0+255]
    int kt_lo2 = qb >= 1 ? qb - 1 : 0;
    int kt_hi2 = qb <= 14 ? qb + 1 : 15;
    int nb2 = kt_hi2 - kt_lo2 + 1;          // 2..3

    // stage the full 128-row Q block into Kb[0]
    cp_tile128(Kb[0], Qg, tid);
    cp_commit();

    if (tid < 128) dsh[tid] = 0.f;
    for (int i = tid; i < 4 * SSTR; i += 256) Ssh[i] = 0.f;
    {   // preload V band (off the critical path)
        const float* Vg = g_V + bh * LSEQ;
        for (int i = tid; i < nb2 * 128; i += 256) Vsh[i] = Vg[kt_lo2 * 128 + i];
    }

    cp_wait0();
    __syncthreads();

    uint32_t Af[2][4][4];                   // [sub][kc][frag] = 32 regs
#pragma unroll
    for (int sub = 0; sub < 2; sub++) {
        uint32_t a_addr =
            sptr(Kb[0] + (sub * 64 + wy * 16 + (lane & 15)) * LDP + ((lane >> 4) << 3));
#pragma unroll
        for (int kc = 0; kc < 4; kc++)
            ldsm4(Af[sub][kc][0], Af[sub][kc][1], Af[sub][kc][2], Af[sub][kc][3],
                  a_addr + kc * 32);
    }
    __syncthreads();                        // done reading Q; Kb reusable

    int g = lane >> 2, tc = lane & 3;
    float dsum[2][2];                       // [sub][hh]
    dsum[0][0] = dsum[0][1] = dsum[1][0] = dsum[1][1] = 0.f;

    // ---- Phase 1: softmax denominators over 16 128-key tiles ----
    cp_tile128(Kb[0], Kg, tid);
    cp_commit();
    for (int kt2 = 0; kt2 < 16; kt2++) {
        int pf = kt2 + 1 < 16 ? kt2 + 1 : 15;       // clamped (idempotent) prefetch
        cp_tile128(Kb[(kt2 + 1) & 1], Kg + pf * 128 * DDIM, tid);
        cp_commit();
        cp_wait1();                                 // current tile landed
        __syncthreads();
#pragma unroll
        for (int hf = 0; hf < 2; hf++) {            // two 64-key halves, no barrier between
            uint32_t acc[2][4][2];
#pragma unroll
            for (int s = 0; s < 2; s++)
#pragma unroll
                for (int n = 0; n < 4; n++) { acc[s][n][0] = 0u; acc[s][n][1] = 0u; }
            mma_h2(Kb[kt2 & 1] + hf * 64 * LDP, Af, acc, lane, wx);
#pragma unroll
            for (int sub = 0; sub < 2; sub++) {
                uint32_t h0 = h2add(h2add(h2ex2(acc[sub][0][0]), h2ex2(acc[sub][1][0])),
                                    h2add(h2ex2(acc[sub][2][0]), h2ex2(acc[sub][3][0])));
                uint32_t h1 = h2add(h2add(h2ex2(acc[sub][0][1]), h2ex2(acc[sub][1][1])),
                                    h2add(h2ex2(acc[sub][2][1]), h2ex2(acc[sub][3][1])));
                float2 f0 = __half22float2(*(__half2*)&h0);
                float2 f1 = __half22float2(*(__half2*)&h1);
                dsum[sub][0] += f0.x + f0.y;
                dsum[sub][1] += f1.x + f1.y;
            }
        }
        __syncthreads();                            // compute done before buffer rewrite
    }
    // reduce over the 4 tc-lanes sharing a row, then shared atomics across warps
#pragma unroll
    for (int sub = 0; sub < 2; sub++)
#pragma unroll
        for (int hh = 0; hh < 2; hh++) {
            dsum[sub][hh] += __shfl_xor_sync(0xffffffffu, dsum[sub][hh], 1);
            dsum[sub][hh] += __shfl_xor_sync(0xffffffffu, dsum[sub][hh], 2);
        }
    if (tc == 0) {
#pragma unroll
        for (int sub = 0; sub < 2; sub++) {
            atomicAdd(&dsh[sub * 64 + wy * 16 + g], dsum[sub][0]);
            atomicAdd(&dsh[sub * 64 + wy * 16 + g + 8], dsum[sub][1]);
        }
    }
    cp_wait0();                             // drain straggler prefetch before buffer reuse
    __syncthreads();

    if (tid < 128) dsh[tid] = 1.f / dsh[tid];
    __syncthreads();                        // dsh inverted

    float inv[2][2];
#pragma unroll
    for (int sub = 0; sub < 2; sub++) {
        inv[sub][0] = dsh[sub * 64 + wy * 16 + g];
        inv[sub][1] = dsh[sub * 64 + wy * 16 + g + 8];
    }

    float* Sbin = Ssh + tc * SSTR;          // this lane's replica (conflict-free in-warp)

    // ---- Phase 2: band tiles, merged-bin epilogue (10 atomics per sub-half) ----
    cp_tile128(Kb[0], Kg + kt_lo2 * 128 * DDIM, tid);
    cp_commit();
    for (int i = 0; i < nb2; i++) {
        int pfi = i + 1 < nb2 ? i + 1 : nb2 - 1;
        cp_tile128(Kb[(i + 1) & 1], Kg + (kt_lo2 + pfi) * 128 * DDIM, tid);
        cp_commit();
        cp_wait1();
        __syncthreads();
        int kt2 = kt_lo2 + i;
#pragma unroll
        for (int hf = 0; hf < 2; hf++) {
            uint32_t acc[2][4][2];
#pragma unroll
            for (int s = 0; s < 2; s++)
#pragma unroll
                for (int n = 0; n < 4; n++) { acc[s][n][0] = 0u; acc[s][n][1] = 0u; }
            mma_h2(Kb[i & 1] + hf * 64 * LDP, Af, acc, lane, wx);

            int kbase = kt2 * 128 + hf * 64 + wx * 32 + tc * 2;  // k at nt=0,cc=0
            int vixb = kbase - kt_lo2 * 128;
            float Vv[4][2];                                       // V per (nt, cc)
#pragma unroll
            for (int nt = 0; nt < 4; nt++) {
                Vv[nt][0] = Vsh[vixb + 8 * nt];
                Vv[nt][1] = Vsh[vixb + 8 * nt + 1];
            }
#pragma unroll
            for (int sub = 0; sub < 2; sub++) {
                float2 e0[4], e1[4];                              // exp per (nt, hh)
#pragma unroll
                for (int nt = 0; nt < 4; nt++) {
                    uint32_t eh0 = h2ex2(acc[sub][nt][0]);
                    uint32_t eh1 = h2ex2(acc[sub][nt][1]);
                    e0[nt] = __half22float2(*(__half2*)&eh0);
                    e1[nt] = __half22float2(*(__half2*)&eh1);
                }
                float iv0 = inv[sub][0], iv1 = inv[sub][1];
                int jb0 = MDIST + kbase - (q0 + sub * 64 + wy * 16 + g);
                // merged diagonals: m = nt - hh in [-1, 3]; hh=0 gives e0[m],
                // hh=1 gives e1[m+1] (its j is shifted by -8 = one nt step)
#pragma unroll
                for (int m = -1; m <= 3; m++) {
                    float vx = 0.f, vy = 0.f;
                    if (m >= 0) {
                        vx += e0[m].x * iv0 * Vv[m][0];
                        vy += e0[m].y * iv0 * Vv[m][1];
                    }
                    if (m < 3) {
                        vx += e1[m + 1].x * iv1 * Vv[m + 1][0];
                        vy += e1[m + 1].y * iv1 * Vv[m + 1][1];
                    }
                    int j = jb0 + 8 * m;
                    if (j >= 0 && j < DBINS) atomicAdd(&Sbin[j], vx);
                    if (j + 1 >= 0 && j + 1 < DBINS) atomicAdd(&Sbin[j + 1], vy);
                }
            }
        }
        __syncthreads();
    }
    cp_wait0();
    __syncthreads();

    // ---- Flush: merge replicas, apply 3-tap window distributively, scatter to out ----
    for (int j = tid; j < DBINS; j += 256)
        Ssh[j] = Ssh[j] + Ssh[SSTR + j] + Ssh[2 * SSTR + j] + Ssh[3 * SSTR + j];
    __syncthreads();
    {
        int h = bh & 7, b = bh >> 3;
        for (int j = tid; j < DBINS; j += 256) {
            float s = Ssh[j];
            float cnt = 1.f;
            if (j > 0)         { s += Ssh[j - 1]; cnt += 1.f; }
            if (j < DBINS - 1) { s += Ssh[j + 1]; cnt += 1.f; }
            atomicAdd(&out[(b * DBINS + j) * NH + h], s / cnt);
        }
    }
}

// ---------------- launch ----------------
extern "C" void kernel_launch(void* const* d_in, const int* in_sizes, int n_in,
                              void* d_out, int out_size) {
    const float* x  = (const float*)d_in[0];
    const float* pe = (const float*)d_in[1];
    const float* Wq = (const float*)d_in[2];
    const float* bq = (const float*)d_in[3];
    const float* Wk = (const float*)d_in[4];
    const float* bk = (const float*)d_in[5];
    const float* Wv = (const float*)d_in[6];
    float* out = (float*)d_out;

    int prep_blocks = PR_BLOCKS + TR_BLOCKS + (NB * DBINS * NH + 255) / 256;
    prep_kernel<<<prep_blocks, 256>>>(x, pe, Wq, Wk, Wv, out);
    proj_kernel<<<dim3(128, 16), 256>>>(bq, bk);
    attn_kernel<<<dim3(16, 32), 256>>>(out);
}

// round 17
// speedup vs baseline: 1.0317x; 1.0317x over previous
#include <cuda_runtime.h>
#include <cuda_fp16.h>
#include <cstdint>

#define LSEQ 2048
#define NH   8
#define DDIM 64
#define NB   4
#define NBH  32          // NB*NH
#define MDIST 128
#define DBINS 257
#define LDP  72          // padded shared row stride (halves): 144B -> conflict-free ldmatrix
#define LOG2E 1.4426950408889634f
#define SSTR 264         // replicated-bin stride (floats); disjoint bank spans per tc

// ---------------- scratch (device globals; no runtime alloc) ----------------
__device__ __half g_qkin[8192 * 256];       // x+pe, fp16
__device__ __half g_Wt[1024 * 256];         // [Wq|Wk]^T, n-major rows, k contiguous
__device__ __half g_Q[NBH * LSEQ * DDIM];   // scaled by d^-0.5 * log2(e), +bias
__device__ __half g_K[NBH * LSEQ * DDIM];
__device__ float  g_V[NBH * LSEQ];          // Vflip[b,h,k] = sigmoid(x[b,L-1-k] . Wv[:,h])

// ---------------- helpers ----------------
__device__ __forceinline__ uint32_t sptr(const void* p) {
    return (uint32_t)__cvta_generic_to_shared(p);
}

__device__ __forceinline__ uint32_t h2ex2(uint32_t x) {   // packed half2 2^x
    uint32_t r;
    asm("ex2.approx.f16x2 %0, %1;\n" : "=r"(r) : "r"(x));
    return r;
}

__device__ __forceinline__ uint32_t h2add(uint32_t a, uint32_t b) {
    uint32_t r;
    asm("add.f16x2 %0, %1, %2;\n" : "=r"(r) : "r"(a), "r"(b));
    return r;
}

__device__ __forceinline__ void ldsm4(uint32_t& r0, uint32_t& r1, uint32_t& r2, uint32_t& r3,
                                      uint32_t addr) {
    asm volatile("ldmatrix.sync.aligned.m8n8.x4.shared.b16 {%0,%1,%2,%3}, [%4];\n"
                 : "=r"(r0), "=r"(r1), "=r"(r2), "=r"(r3) : "r"(addr));
}

// f16-accumulate MMA: C/D = 2 packed-half2 regs
__device__ __forceinline__ void mma16816h(uint32_t& c0, uint32_t& c1, uint32_t a0, uint32_t a1,
                                          uint32_t a2, uint32_t a3, uint32_t b0, uint32_t b1) {
    asm volatile(
        "mma.sync.aligned.m16n8k16.row.col.f16.f16.f16.f16 "
        "{%0,%1},{%2,%3,%4,%5},{%6,%7},{%0,%1};\n"
        : "+r"(c0), "+r"(c1)
        : "r"(a0), "r"(a1), "r"(a2), "r"(a3), "r"(b0), "r"(b1));
}

__device__ __forceinline__ void cp_async16(uint32_t dst, const void* src) {
    asm volatile("cp.async.ca.shared.global [%0], [%1], 16;\n" :: "r"(dst), "l"(src));
}
__device__ __forceinline__ void cp_commit() { asm volatile("cp.async.commit_group;\n"); }
__device__ __forceinline__ void cp_wait0()  { asm volatile("cp.async.wait_group 0;\n"); }

// async copy of a 64x64 half tile into padded shared tile (global row stride = stride)
__device__ __forceinline__ void cp_tile_s(__half* dst, const __half* src, int stride, int tid) {
    int r = tid >> 3, c = (tid & 7) << 3;
    cp_async16(sptr(dst + r * LDP + c), src + r * stride + c);
    cp_async16(sptr(dst + (r + 32) * LDP + c), src + (r + 32) * stride + c);
}

// async copy of a 128x64 half tile (global row stride = 64)
__device__ __forceinline__ void cp_tile128(__half* dst, const __half* src, int tid) {
    int r = tid >> 3, c = (tid & 7) << 3;
#pragma unroll
    for (int rr = 0; rr < 4; rr++)
        cp_async16(sptr(dst + (r + rr * 32) * LDP + c), src + (r + rr * 32) * 64 + c);
}

// Dual-subtile MMA (attention): B fragments loaded once, applied to both Q subtiles.
__device__ __forceinline__ void mma_h2(const __half* Ks, const uint32_t Af[2][4][4],
                                       uint32_t acc[2][4][2], int lane, int wx) {
    int brow = wx * 32 + (lane & 7) + ((lane >> 4) << 3);
    int bcol = ((lane >> 3) & 1) << 3;
    uint32_t b_addr0 = sptr(Ks + brow * LDP + bcol);
    uint32_t b_addr1 = b_addr0 + 16 * LDP * 2;
#pragma unroll
    for (int kc = 0; kc < 4; kc++) {
        uint32_t b0, b1, b2, b3, b4, b5, b6, b7;
        ldsm4(b0, b1, b2, b3, b_addr0 + kc * 32);
        ldsm4(b4, b5, b6, b7, b_addr1 + kc * 32);
#pragma unroll
        for (int sub = 0; sub < 2; sub++) {
            mma16816h(acc[sub][0][0], acc[sub][0][1], Af[sub][kc][0], Af[sub][kc][1],
                      Af[sub][kc][2], Af[sub][kc][3], b0, b1);
            mma16816h(acc[sub][1][0], acc[sub][1][1], Af[sub][kc][0], Af[sub][kc][1],
                      Af[sub][kc][2], Af[sub][kc][3], b2, b3);
            mma16816h(acc[sub][2][0], acc[sub][2][1], Af[sub][kc][0], Af[sub][kc][1],
                      Af[sub][kc][2], Af[sub][kc][3], b4, b5);
            mma16816h(acc[sub][3][0], acc[sub][3][1], Af[sub][kc][0], Af[sub][kc][1],
                      Af[sub][kc][2], Af[sub][kc][3], b6, b7);
        }
    }
}

// 64x64 mma, A+B from shared, f16 acc (proj kernel, 4x2 warp grid, 16x32/warp)
__device__ __forceinline__ void mma_tile_64h(const __half* Qs, const __half* Ks,
                                             uint32_t acc[4][2], int lane, int wy, int wx) {
    uint32_t a_addr = sptr(Qs + (wy * 16 + (lane & 15)) * LDP + ((lane >> 4) << 3));
    int brow = wx * 32 + (lane & 7) + ((lane >> 4) << 3);
    int bcol = ((lane >> 3) & 1) << 3;
    uint32_t b_addr0 = sptr(Ks + brow * LDP + bcol);
    uint32_t b_addr1 = b_addr0 + 16 * LDP * 2;
#pragma unroll
    for (int kc = 0; kc < 4; kc++) {
        uint32_t a0, a1, a2, a3, b0, b1, b2, b3, b4, b5, b6, b7;
        ldsm4(a0, a1, a2, a3, a_addr + kc * 32);
        ldsm4(b0, b1, b2, b3, b_addr0 + kc * 32);
        ldsm4(b4, b5, b6, b7, b_addr1 + kc * 32);
        mma16816h(acc[0][0], acc[0][1], a0, a1, a2, a3, b0, b1);
        mma16816h(acc[1][0], acc[1][1], a0, a1, a2, a3, b2, b3);
        mma16816h(acc[2][0], acc[2][1], a0, a1, a2, a3, b4, b5);
        mma16816h(acc[3][0], acc[3][1], a0, a1, a2, a3, b6, b7);
    }
}

// ---------------- kernel 1: prep (R15 config: row blocks + tiled W transpose) --------
#define PR_BLOCKS 512           // 8192 rows / 16 rows per block
#define TR_BLOCKS 64            // 2 weights x (4 kk-tiles x 8 n-tiles)
#define XP 264                  // padded float row stride (float4-aligned)
__global__ void __launch_bounds__(256) prep_kernel(const float* __restrict__ x,
                                                   const float* __restrict__ pe,
                                                   const float* __restrict__ Wq,
                                                   const float* __restrict__ Wk,
                                                   const float* __restrict__ Wv,
                                                   float* __restrict__ out) {
    __shared__ float Sh[24 * XP];           // row blocks: Xsh[16*XP] + Wsh[8*XP]
                                            // transpose blocks: Tsh[64*65] (4160 floats)
    int bid = blockIdx.x, tid = threadIdx.x;
    if (bid < PR_BLOCKS) {
        float* Xsh = Sh;
        float* Wsh = Sh + 16 * XP;          // Wv transposed: [h][kk]
        for (int i = tid; i < 2048; i += 256) {
            int kk = i >> 3, h = i & 7;
            Wsh[h * XP + kk] = Wv[i];
        }
        int row0 = bid * 16;
        for (int i = tid; i < 1024; i += 256) {
            int r = i >> 6, c4 = (i & 63) << 2;
            *(float4*)(Xsh + r * XP + c4) = *(const float4*)(x + (row0 + r) * 256 + c4);
        }
        __syncthreads();
        // qkin = x + pe -> f16 (vectorized)
        for (int i = tid; i < 1024; i += 256) {
            int r = i >> 6, c4 = (i & 63) << 2;
            int l = (row0 + r) & (LSEQ - 1);
            float4 p = *(const float4*)(pe + l * 256 + c4);
            float4 xv = *(const float4*)(Xsh + r * XP + c4);
            __half2 h0 = __floats2half2_rn(xv.x + p.x, xv.y + p.y);
            __half2 h1 = __floats2half2_rn(xv.z + p.z, xv.w + p.w);
            uint2 st;
            st.x = *(uint32_t*)&h0;
            st.y = *(uint32_t*)&h1;
            *(uint2*)(g_qkin + (row0 + r) * 256 + c4) = st;
        }
        // V = sigmoid(x . Wv), flipped; 2 threads per (row, h), float4 dot
        int task = tid >> 1, halfi = tid & 1;
        int r = task >> 3, h = task & 7;
        const float* xr = Xsh + r * XP + halfi * 128;
        const float* wr = Wsh + h * XP + halfi * 128;
        float s = 0.f;
#pragma unroll
        for (int kk = 0; kk < 128; kk += 4) {
            float4 a = *(const float4*)(xr + kk);
            float4 b = *(const float4*)(wr + kk);
            s += a.x * b.x + a.y * b.y + a.z * b.z + a.w * b.w;
        }
        s += __shfl_xor_sync(0xffffffffu, s, 1);
        if (halfi == 0) {
            int bl = row0 + r;
            float v = 1.f / (1.f + __expf(-s));
            int b = bl >> 11, l = bl & (LSEQ - 1);
            g_V[(b * NH + h) * LSEQ + (LSEQ - 1 - l)] = v;
        }
    } else if (bid < PR_BLOCKS + TR_BLOCKS) {
        // coalesced tiled transpose of Wq/Wk into g_Wt (n-major, kk contiguous)
        int tb = bid - PR_BLOCKS;
        int which = tb >> 5;                // 0 = Wq, 1 = Wk
        int t = tb & 31;
        int kk0 = (t >> 3) << 6;            // 4 kk-tiles
        int n0 = (t & 7) << 6;              // 8 n-tiles
        const float* W = which ? Wk : Wq;
        float* Tsh = Sh;                    // 64 x 65 staging
        for (int i = tid; i < 4096; i += 256) {
            int r = i >> 6, c = i & 63;     // r = local kk, c = local n (coalesced read)
            Tsh[c * 65 + r] = W[(kk0 + r) * 512 + n0 + c];
        }
        __syncthreads();
        for (int i = tid; i < 4096; i += 256) {
            int n = i >> 6, kk = i & 63;    // contiguous half writes along kk
            g_Wt[(which * 512 + n0 + n) * 256 + kk0 + kk] = __float2half(Tsh[n * 65 + kk]);
        }
    } else {
        int idx = (bid - PR_BLOCKS - TR_BLOCKS) * 256 + tid;
        if (idx < NB * DBINS * NH) out[idx] = 0.f;  // attn scatters into out
    }
}

// ---------------- kernel 2: Q/K projection GEMM (f16 acc, cp.async 2-stage) ---------
__global__ void __launch_bounds__(256) proj_kernel(const float* __restrict__ bq,
                                                   const float* __restrict__ bk) {
    __shared__ __half As[2][64 * LDP];
    __shared__ __half Bs[2][64 * LDP];
    int tid = threadIdx.x, lane = tid & 31, w = tid >> 5, wy = w >> 1, wx = w & 1;
    int m0 = blockIdx.x << 6, n0 = blockIdx.y << 6;
    const __half* Ag = g_qkin + m0 * 256;
    const __half* Bg = g_Wt + n0 * 256;

    uint32_t acc[4][2];
#pragma unroll
    for (int i = 0; i < 4; i++) { acc[i][0] = 0u; acc[i][1] = 0u; }

    // stage 0
    cp_tile_s(As[0], Ag, 256, tid);
    cp_tile_s(Bs[0], Bg, 256, tid);
    cp_commit();

#define PROJ_STEP(KS, WAITN)                                                     \
    {                                                                            \
        if ((KS) + 1 < 4) {                                                      \
            cp_tile_s(As[((KS) + 1) & 1], Ag + ((KS) + 1) * 64, 256, tid);       \
            cp_tile_s(Bs[((KS) + 1) & 1], Bg + ((KS) + 1) * 64, 256, tid);       \
            cp_commit();                                                         \
        }                                                                        \
        asm volatile("cp.async.wait_group %0;\n" ::"n"(WAITN));                  \
        __syncthreads();                                                         \
        mma_tile_64h(As[(KS) & 1], Bs[(KS) & 1], acc, lane, wy, wx);             \
        __syncthreads();                                                         \
    }
    PROJ_STEP(0, 1)
    PROJ_STEP(1, 1)
    PROJ_STEP(2, 1)
    PROJ_STEP(3, 0)
#undef PROJ_STEP

    int g = lane >> 2, tc = lane & 3;
#pragma unroll
    for (int nt = 0; nt < 4; nt++) {
#pragma unroll
        for (int hh = 0; hh < 2; hh++) {
            float2 v = __half22float2(*(__half2*)&acc[nt][hh]);
            int row = m0 + wy * 16 + g + (hh << 3);
            int col = n0 + wx * 32 + nt * 8 + tc * 2;
            int b = row >> 11, l = row & (LSEQ - 1);
            if (col < 512) {
                // fold d^-0.5 and log2(e) into Q so score-exp is a single ex2
                float v0 = (v.x + bq[col]) * (0.125f * LOG2E);
                float v1 = (v.y + bq[col + 1]) * (0.125f * LOG2E);
                int hd = col >> 6, dd = col & 63;
                *(__half2*)(g_Q + ((b * NH + hd) * LSEQ + l) * DDIM + dd) =
                    __floats2half2_rn(v0, v1);
            } else {
                int cj = col - 512;
                float v0 = v.x + bk[cj];
                float v1 = v.y + bk[cj + 1];
                int hd = cj >> 6, dd = cj & 63;
                *(__half2*)(g_K + ((b * NH + hd) * LSEQ + l) * DDIM + dd) =
                    __floats2half2_rn(v0, v1);
            }
        }
    }
}

// ---------------- kernel 3: attention (1 barrier per pipeline iteration) -------------
__global__ void __launch_bounds__(256, 4) attn_kernel(float* __restrict__ out) {
    __shared__ __half Kb[2][128 * LDP];     // double-buffered 128-key tiles; Kb[0] stages Q
    __shared__ float dsh[128];
    __shared__ float Ssh[4 * SSTR];         // 4 bank-replicated bin arrays (by tc)
    __shared__ float Vsh[3 * 128];

    int tid = threadIdx.x, lane = tid & 31, w = tid >> 5, wy = w >> 1, wx = w & 1;
    int qb = blockIdx.x, bh = blockIdx.y;   // qb: 128-row Q block (0..15)
    int q0 = qb << 7;
    const __half* Qg = g_Q + (bh * LSEQ + q0) * DDIM;
    const __half* Kg = g_K + bh * LSEQ * DDIM;

    // band 128-key tiles for q in [q0, q0+127]: k in [q0-128, q0+255]
    int kt_lo2 = qb >= 1 ? qb - 1 : 0;
    int kt_hi2 = qb <= 14 ? qb + 1 : 15;
    int nb2 = kt_hi2 - kt_lo2 + 1;          // 2..3

    // stage the full 128-row Q block into Kb[0]
    cp_tile128(Kb[0], Qg, tid);
    cp_commit();

    if (tid < 128) dsh[tid] = 0.f;
    for (int i = tid; i < 4 * SSTR; i += 256) Ssh[i] = 0.f;
    {   // preload V band (off the critical path)
        const float* Vg = g_V + bh * LSEQ;
        for (int i = tid; i < nb2 * 128; i += 256) Vsh[i] = Vg[kt_lo2 * 128 + i];
    }

    cp_wait0();
    __syncthreads();

    uint32_t Af[2][4][4];                   // [sub][kc][frag] = 32 regs
#pragma unroll
    for (int sub = 0; sub < 2; sub++) {
        uint32_t a_addr =
            sptr(Kb[0] + (sub * 64 + wy * 16 + (lane & 15)) * LDP + ((lane >> 4) << 3));
#pragma unroll
        for (int kc = 0; kc < 4; kc++)
            ldsm4(Af[sub][kc][0], Af[sub][kc][1], Af[sub][kc][2], Af[sub][kc][3],
                  a_addr + kc * 32);
    }
    __syncthreads();                        // done reading Q; Kb reusable

    int g = lane >> 2, tc = lane & 3;
    float dsum[2][2];                       // [sub][hh]
    dsum[0][0] = dsum[0][1] = dsum[1][0] = dsum[1][1] = 0.f;

    // ---- Phase 1: denominators over 16 tiles; 1 barrier/iter (prefetch AFTER sync,
    //      so the top barrier orders prior compute before the buffer overwrite) ----
    cp_tile128(Kb[0], Kg, tid);
    cp_commit();
    for (int kt2 = 0; kt2 < 16; kt2++) {
        cp_wait0();                                 // current tile landed
        __syncthreads();                            // all warps past previous compute
        if (kt2 + 1 < 16) {
            cp_tile128(Kb[(kt2 + 1) & 1], Kg + (kt2 + 1) * 128 * DDIM, tid);
            cp_commit();
        }
#pragma unroll
        for (int hf = 0; hf < 2; hf++) {            // two 64-key halves, no barrier between
            uint32_t acc[2][4][2];
#pragma unroll
            for (int s = 0; s < 2; s++)
#pragma unroll
                for (int n = 0; n < 4; n++) { acc[s][n][0] = 0u; acc[s][n][1] = 0u; }
            mma_h2(Kb[kt2 & 1] + hf * 64 * LDP, Af, acc, lane, wx);
#pragma unroll
            for (int sub = 0; sub < 2; sub++) {
                uint32_t h0 = h2add(h2add(h2ex2(acc[sub][0][0]), h2ex2(acc[sub][1][0])),
                                    h2add(h2ex2(acc[sub][2][0]), h2ex2(acc[sub][3][0])));
                uint32_t h1 = h2add(h2add(h2ex2(acc[sub][0][1]), h2ex2(acc[sub][1][1])),
                                    h2add(h2ex2(acc[sub][2][1]), h2ex2(acc[sub][3][1])));
                float2 f0 = __half22float2(*(__half2*)&h0);
                float2 f1 = __half22float2(*(__half2*)&h1);
                dsum[sub][0] += f0.x + f0.y;
                dsum[sub][1] += f1.x + f1.y;
            }
        }
    }
    // reduce over the 4 tc-lanes sharing a row, then shared atomics across warps
#pragma unroll
    for (int sub = 0; sub < 2; sub++)
#pragma unroll
        for (int hh = 0; hh < 2; hh++) {
            dsum[sub][hh] += __shfl_xor_sync(0xffffffffu, dsum[sub][hh], 1);
            dsum[sub][hh] += __shfl_xor_sync(0xffffffffu, dsum[sub][hh], 2);
        }
    if (tc == 0) {
#pragma unroll
        for (int sub = 0; sub < 2; sub++) {
            atomicAdd(&dsh[sub * 64 + wy * 16 + g], dsum[sub][0]);
            atomicAdd(&dsh[sub * 64 + wy * 16 + g + 8], dsum[sub][1]);
        }
    }
    __syncthreads();                        // all compute + atomics done

    if (tid < 128) dsh[tid] = 1.f / dsh[tid];
    __syncthreads();                        // dsh inverted; Kb free

    float inv[2][2];
#pragma unroll
    for (int sub = 0; sub < 2; sub++) {
        inv[sub][0] = dsh[sub * 64 + wy * 16 + g];
        inv[sub][1] = dsh[sub * 64 + wy * 16 + g + 8];
    }

    float* Sbin = Ssh + tc * SSTR;          // this lane's replica (conflict-free in-warp)

    // ---- Phase 2: band tiles, merged-bin epilogue; 1 barrier/iter ----
    cp_tile128(Kb[0], Kg + kt_lo2 * 128 * DDIM, tid);
    cp_commit();
    for (int i = 0; i < nb2; i++) {
        cp_wait0();
        __syncthreads();
        if (i + 1 < nb2) {
            cp_tile128(Kb[(i + 1) & 1], Kg + (kt_lo2 + i + 1) * 128 * DDIM, tid);
            cp_commit();
        }
        int kt2 = kt_lo2 + i;
#pragma unroll
        for (int hf = 0; hf < 2; hf++) {
            uint32_t acc[2][4][2];
#pragma unroll
            for (int s = 0; s < 2; s++)
#pragma unroll
                for (int n = 0; n < 4; n++) { acc[s][n][0] = 0u; acc[s][n][1] = 0u; }
            mma_h2(Kb[i & 1] + hf * 64 * LDP, Af, acc, lane, wx);

            int kbase = kt2 * 128 + hf * 64 + wx * 32 + tc * 2;  // k at nt=0,cc=0
            int vixb = kbase - kt_lo2 * 128;
            float Vv[4][2];                                       // V per (nt, cc)
#pragma unroll
            for (int nt = 0; nt < 4; nt++) {
                Vv[nt][0] = Vsh[vixb + 8 * nt];
                Vv[nt][1] = Vsh[vixb + 8 * nt + 1];
            }
#pragma unroll
            for (int sub = 0; sub < 2; sub++) {
                float2 e0[4], e1[4];                              // exp per (nt, hh)
#pragma unroll
                for (int nt = 0; nt < 4; nt++) {
                    uint32_t eh0 = h2ex2(acc[sub][nt][0]);
                    uint32_t eh1 = h2ex2(acc[sub][nt][1]);
                    e0[nt] = __half22float2(*(__half2*)&eh0);
                    e1[nt] = __half22float2(*(__half2*)&eh1);
                }
                float iv0 = inv[sub][0], iv1 = inv[sub][1];
                int jb0 = MDIST + kbase - (q0 + sub * 64 + wy * 16 + g);
                // merged diagonals: m = nt - hh in [-1, 3]; hh=0 gives e0[m],
                // hh=1 gives e1[m+1] (its j is shifted by -8 = one nt step)
#pragma unroll
                for (int m = -1; m <= 3; m++) {
                    float vx = 0.f, vy = 0.f;
                    if (m >= 0) {
                        vx += e0[m].x * iv0 * Vv[m][0];
                        vy += e0[m].y * iv0 * Vv[m][1];
                    }
                    if (m < 3) {
                        vx += e1[m + 1].x * iv1 * Vv[m + 1][0];
                        vy += e1[m + 1].y * iv1 * Vv[m + 1][1];
                    }
                    int j = jb0 + 8 * m;
                    if (j >= 0 && j < DBINS) atomicAdd(&Sbin[j], vx);
                    if (j + 1 >= 0 && j + 1 < DBINS) atomicAdd(&Sbin[j + 1], vy);
                }
            }
        }
    }
    __syncthreads();

    // ---- Flush: merge replicas, apply 3-tap window distributively, scatter to out ----
    for (int j = tid; j < DBINS; j += 256)
        Ssh[j] = Ssh[j] + Ssh[SSTR + j] + Ssh[2 * SSTR + j] + Ssh[3 * SSTR + j];
    __syncthreads();
    {
        int h = bh & 7, b = bh >> 3;
        for (int j = tid; j < DBINS; j += 256) {
            float s = Ssh[j];
            float cnt = 1.f;
            if (j > 0)         { s += Ssh[j - 1]; cnt += 1.f; }
            if (j < DBINS - 1) { s += Ssh[j + 1]; cnt += 1.f; }
            atomicAdd(&out[(b * DBINS + j) * NH + h], s / cnt);
        }
    }
}

// ---------------- launch ----------------
extern "C" void kernel_launch(void* const* d_in, const int* in_sizes, int n_in,
                              void* d_out, int out_size) {
    const float* x  = (const float*)d_in[0];
    const float* pe = (const float*)d_in[1];
    const float* Wq = (const float*)d_in[2];
    const float* bq = (const float*)d_in[3];
    const float* Wk = (const float*)d_in[4];
    const float* bk = (const float*)d_in[5];
    const float* Wv = (const float*)d_in[6];
    float* out = (float*)d_out;

    int prep_blocks = PR_BLOCKS + TR_BLOCKS + (NB * DBINS * NH + 255) / 256;
    prep_kernel<<<prep_blocks, 256>>>(x, pe, Wq, Wk, Wv, out);
    proj_kernel<<<dim3(128, 16), 256>>>(bq, bk);
    attn_kernel<<<dim3(16, 32), 256>>>(out);
}